// round 9
// baseline (speedup 1.0000x reference)
#include <cuda_runtime.h>
#include <cstdint>
#include <cstddef>

#define S_LEN 4096
#define BATCH 8
#define DH    512
#define DIN   2048
#define M_TOT (S_LEN * BATCH)
#define CLUSTER 16
#define RPC   32

__device__ float g_seq[(size_t)M_TOT * DH];
__device__ float g_G[(size_t)M_TOT * 3 * DH];

// ================= GEMM1: seq = x @ Wlm^T (M=32768,N=512,K=2048) ===============
__global__ __launch_bounds__(256) void gemm1_kernel(const float* __restrict__ x,
                                                    const float* __restrict__ Wlm) {
    __shared__ float As[16][132], Bs[16][132];
    const int m0 = blockIdx.y * 128, n0 = blockIdx.x * 128, tid = threadIdx.x;
    const int tx = tid & 15, ty = tid >> 4;
    float acc[8][8] = {};
    for (int k0 = 0; k0 < DIN; k0 += 16) {
#pragma unroll
        for (int i = 0; i < 2; i++) {
            int f = tid * 2 + i, m = f >> 2, kq = f & 3;
            int gm = m0 + m, b = gm & 7, t = gm >> 3;
            float4 v = *reinterpret_cast<const float4*>(x + ((size_t)b * S_LEN + t) * DIN + k0 + kq * 4);
            As[kq*4+0][m] = v.x; As[kq*4+1][m] = v.y; As[kq*4+2][m] = v.z; As[kq*4+3][m] = v.w;
        }
#pragma unroll
        for (int i = 0; i < 2; i++) {
            int f = tid * 2 + i, n = f >> 2, kq = f & 3;
            float4 v = *reinterpret_cast<const float4*>(Wlm + (size_t)(n0 + n) * DIN + k0 + kq * 4);
            Bs[kq*4+0][n] = v.x; Bs[kq*4+1][n] = v.y; Bs[kq*4+2][n] = v.z; Bs[kq*4+3][n] = v.w;
        }
        __syncthreads();
#pragma unroll
        for (int kk = 0; kk < 16; kk++) {
            float4 a0 = *(const float4*)&As[kk][ty*8], a1 = *(const float4*)&As[kk][ty*8+4];
            float4 b0 = *(const float4*)&Bs[kk][tx*4], b1 = *(const float4*)&Bs[kk][64+tx*4];
            float a[8] = {a0.x,a0.y,a0.z,a0.w,a1.x,a1.y,a1.z,a1.w};
            float bb[8] = {b0.x,b0.y,b0.z,b0.w,b1.x,b1.y,b1.z,b1.w};
#pragma unroll
            for (int i = 0; i < 8; i++)
#pragma unroll
                for (int j = 0; j < 8; j++) acc[i][j] = fmaf(a[i], bb[j], acc[i][j]);
        }
        __syncthreads();
    }
#pragma unroll
    for (int i = 0; i < 8; i++) {
        size_t row = (size_t)(m0 + ty * 8 + i) * DH;
        *(float4*)&g_seq[row + n0 + tx*4]      = make_float4(acc[i][0],acc[i][1],acc[i][2],acc[i][3]);
        *(float4*)&g_seq[row + n0 + 64 + tx*4] = make_float4(acc[i][4],acc[i][5],acc[i][6],acc[i][7]);
    }
}

// ============ GEMM2: G = seq @ [Wzx|Wrx|Whx]^T (M=32768,N=1536,K=512) ==========
__global__ __launch_bounds__(256) void gemm2_kernel(const float* __restrict__ Wz,
                                                    const float* __restrict__ Wr,
                                                    const float* __restrict__ Wh) {
    __shared__ float As[16][132], Bs[16][132];
    const int m0 = blockIdx.y * 128, n0 = blockIdx.x * 128, tid = threadIdx.x;
    const int tx = tid & 15, ty = tid >> 4;
    const float* base = (n0 < 512) ? Wz : (n0 < 1024) ? Wr : Wh;
    const int br0 = n0 & 511;
    float acc[8][8] = {};
    for (int k0 = 0; k0 < DH; k0 += 16) {
#pragma unroll
        for (int i = 0; i < 2; i++) {
            int f = tid * 2 + i, m = f >> 2, kq = f & 3;
            float4 v = *reinterpret_cast<const float4*>(g_seq + (size_t)(m0 + m) * DH + k0 + kq * 4);
            As[kq*4+0][m] = v.x; As[kq*4+1][m] = v.y; As[kq*4+2][m] = v.z; As[kq*4+3][m] = v.w;
        }
#pragma unroll
        for (int i = 0; i < 2; i++) {
            int f = tid * 2 + i, n = f >> 2, kq = f & 3;
            float4 v = *reinterpret_cast<const float4*>(base + (size_t)(br0 + n) * 1024 + k0 + kq * 4);
            Bs[kq*4+0][n] = v.x; Bs[kq*4+1][n] = v.y; Bs[kq*4+2][n] = v.z; Bs[kq*4+3][n] = v.w;
        }
        __syncthreads();
#pragma unroll
        for (int kk = 0; kk < 16; kk++) {
            float4 a0 = *(const float4*)&As[kk][ty*8], a1 = *(const float4*)&As[kk][ty*8+4];
            float4 b0 = *(const float4*)&Bs[kk][tx*4], b1 = *(const float4*)&Bs[kk][64+tx*4];
            float a[8] = {a0.x,a0.y,a0.z,a0.w,a1.x,a1.y,a1.z,a1.w};
            float bb[8] = {b0.x,b0.y,b0.z,b0.w,b1.x,b1.y,b1.z,b1.w};
#pragma unroll
            for (int i = 0; i < 8; i++)
#pragma unroll
                for (int j = 0; j < 8; j++) acc[i][j] = fmaf(a[i], bb[j], acc[i][j]);
        }
        __syncthreads();
    }
#pragma unroll
    for (int i = 0; i < 8; i++) {
        size_t row = (size_t)(m0 + ty * 8 + i) * 1536;
        *(float4*)&g_G[row + n0 + tx*4]      = make_float4(acc[i][0],acc[i][1],acc[i][2],acc[i][3]);
        *(float4*)&g_G[row + n0 + 64 + tx*4] = make_float4(acc[i][4],acc[i][5],acc[i][6],acc[i][7]);
    }
}

// ================= helpers =================
__device__ __forceinline__ uint32_t smem_u32(const void* p) {
    return (uint32_t)__cvta_generic_to_shared(p);
}
__device__ __forceinline__ uint32_t dsmem_map(uint32_t a, unsigned r) {
    uint32_t x; asm("mapa.shared::cluster.u32 %0, %1, %2;" : "=r"(x) : "r"(a), "r"(r)); return x;
}
// bulk DSMEM copy: local smem -> remote smem, tx-credits the remote mbarrier
__device__ __forceinline__ void dsmem_bulk(uint32_t dst, uint32_t src, uint32_t bytes, uint32_t mbar) {
    asm volatile("cp.async.bulk.shared::cluster.shared::cta.mbarrier::complete_tx::bytes "
                 "[%0], [%1], %2, [%3];"
                 :: "r"(dst), "r"(src), "r"(bytes), "r"(mbar) : "memory");
}
__device__ __forceinline__ void fence_proxy_async_cta() {
    asm volatile("fence.proxy.async.shared::cta;" ::: "memory");
}
__device__ __forceinline__ void mbar_init(uint32_t a, uint32_t cnt) {
    asm volatile("mbarrier.init.shared.b64 [%0], %1;" :: "r"(a), "r"(cnt) : "memory");
}
__device__ __forceinline__ void mbar_arrive(uint32_t a) {
    asm volatile("mbarrier.arrive.shared.b64 _, [%0];" :: "r"(a) : "memory");
}
__device__ __forceinline__ void mbar_expect_tx(uint32_t a, uint32_t tx) {
    asm volatile("mbarrier.arrive.expect_tx.shared.b64 _, [%0], %1;" :: "r"(a), "r"(tx) : "memory");
}
__device__ __forceinline__ void mbar_wait(uint32_t a, uint32_t parity) {
    uint32_t done;
    asm volatile("{\n\t.reg .pred p;\n\t"
                 "mbarrier.try_wait.parity.shared.b64 p, [%1], %2;\n\t"
                 "selp.b32 %0, 1, 0, p;\n\t}"
                 : "=r"(done) : "r"(a), "r"(parity) : "memory");
    while (!done) {
        asm volatile("{\n\t.reg .pred p;\n\t"
                     "mbarrier.try_wait.parity.shared.b64 p, [%1], %2;\n\t"
                     "selp.b32 %0, 1, 0, p;\n\t}"
                     : "=r"(done) : "r"(a), "r"(parity) : "memory");
    }
}
__device__ __forceinline__ void cl_sync() {
    asm volatile("barrier.cluster.arrive.aligned;" ::: "memory");
    asm volatile("barrier.cluster.wait.aligned;"   ::: "memory");
}
__device__ __forceinline__ float sigmoidf_(float v) { return 1.f / (1.f + __expf(-v)); }

// == GRU: 8 clusters x 16 CTAs x 512 thr; bulk-aggregated DSMEM exchange ========
__global__ void __cluster_dims__(CLUSTER, 1, 1) __launch_bounds__(512, 1)
gru_kernel(const float* __restrict__ Wz, const float* __restrict__ Wr,
           const float* __restrict__ Wh, const float* __restrict__ Wc,
           float* __restrict__ out) {
    extern __shared__ float sm[];
    float* wAll  = sm;                    // [96][512]: r 0-31, z 32-63, h 64-95
    float* hbuf  = sm + 96 * 512;         // [2][512]
    float* rhbf  = hbuf + 1024;           // [2][512]
    float* zbuf  = rhbf + 1024;           // [32]
    float* stg_rh = zbuf + 32;            // [32] staging (16B aligned)
    float* stg_h  = stg_rh + 32;          // [32]
    uint32_t mb_rh = smem_u32(stg_h + 32);   // 8B each
    uint32_t mb_h  = mb_rh + 8;
    uint32_t mb_z  = mb_rh + 16;

    const int tid = threadIdx.x;
    unsigned rank; asm("mov.u32 %0, %%cluster_ctarank;" : "=r"(rank));
    const int b  = blockIdx.x / CLUSTER;
    const int j0 = (int)rank * RPC;
    const int w = tid >> 5, l = tid & 31;

    for (int i = tid; i < 32 * 128; i += 512) {
        int r = i >> 7, q = (i & 127) * 4;
        *(float4*)&wAll[r * 512 + q]        = *(const float4*)(Wr + (size_t)(j0 + r) * 1024 + 512 + q);
        *(float4*)&wAll[(32 + r) * 512 + q] = *(const float4*)(Wz + (size_t)(j0 + r) * 1024 + 512 + q);
        *(float4*)&wAll[(64 + r) * 512 + q] = *(const float4*)(Wh + (size_t)(j0 + r) * 1024 + 512 + q);
    }
    for (int i = tid; i < 1024; i += 512) hbuf[i] = 0.f;
    if (tid == 0) { mbar_init(mb_rh, 1); mbar_init(mb_h, 1); mbar_init(mb_z, 16); }
    __syncthreads();

    const bool isR = (w < 8);
    const int lw  = isR ? w : (w - 8);
    const int lr0 = lw * 4;
    const int half = l >> 4;
    const int r0 = lr0 + half * 2;
    const unsigned rk = (unsigned)(l & 15);

    // bulk-copy endpoints (warp 0 lanes 0..15; lane == destination rank)
    uint32_t rh_d0 = 0, rh_d1 = 0, h_d0 = 0, h_d1 = 0, mrh_r = 0, mh_r = 0;
    if (w == 0 && l < 16) {
        rh_d0 = dsmem_map(smem_u32(&rhbf[0 * 512 + j0]), (unsigned)l);
        rh_d1 = dsmem_map(smem_u32(&rhbf[1 * 512 + j0]), (unsigned)l);
        h_d0  = dsmem_map(smem_u32(&hbuf[0 * 512 + j0]), (unsigned)l);
        h_d1  = dsmem_map(smem_u32(&hbuf[1 * 512 + j0]), (unsigned)l);
        mrh_r = dsmem_map(mb_rh, (unsigned)l);
        mh_r  = dsmem_map(mb_h, (unsigned)l);
    }
    const uint32_t src_rh = smem_u32(stg_rh), src_h = smem_u32(stg_h);

    const size_t gx_a = (isR ? 512 : 0) + j0 + r0;
    const size_t gx_h = 1024 + j0 + r0;

    cl_sync();                                    // mbars + h0 + weights live

    float ga0 = __ldcs(g_G + (size_t)b * 1536 + gx_a);
    float ga1 = __ldcs(g_G + (size_t)b * 1536 + gx_a + 1);
    float gh0 = 0.f, gh1 = 0.f;
    if (isR) {
        gh0 = __ldcs(g_G + (size_t)b * 1536 + gx_h);
        gh1 = __ldcs(g_G + (size_t)b * 1536 + gx_h + 1);
    }

    int p = 0;
    uint32_t ph = 0;
    for (int t = 0; t < S_LEN; t++) {
        if (tid == 0) {                            // arm tx budgets (16 x 128B)
            mbar_expect_tx(mb_rh, 2048);
            mbar_expect_tx(mb_h, 2048);
        }
        const int tn = (t + 1 < S_LEN) ? t + 1 : t;
        const size_t gbn = ((size_t)tn * 8 + b) * 1536;
        float gna0, gna1, gnh0 = 0.f, gnh1 = 0.f;
        const int rb = t & 1;

        if (isR) {
            // ---- r pre-acts ----
            float4 h4[4];
#pragma unroll
            for (int q = 0; q < 4; q++) h4[q] = *(const float4*)&hbuf[p * 512 + q * 128 + l * 4];
            float a[4];
#pragma unroll
            for (int i = 0; i < 4; i++) {
                float s = 0.f;
#pragma unroll
                for (int q = 0; q < 4; q++) {
                    float4 w4 = *(const float4*)&wAll[(lr0 + i) * 512 + q * 128 + l * 4];
                    s = fmaf(w4.x, h4[q].x, s); s = fmaf(w4.y, h4[q].y, s);
                    s = fmaf(w4.z, h4[q].z, s); s = fmaf(w4.w, h4[q].w, s);
                }
#pragma unroll
                for (int d = 16; d; d >>= 1) s += __shfl_xor_sync(~0u, s, d);
                a[i] = s;
            }
            if (rk == 0) {
                stg_rh[r0]     = sigmoidf_(a[half * 2]     + ga0) * hbuf[p * 512 + j0 + r0];
                stg_rh[r0 + 1] = sigmoidf_(a[half * 2 + 1] + ga1) * hbuf[p * 512 + j0 + r0 + 1];
            }
            asm volatile("bar.sync 1, 256;" ::: "memory");
            if (w == 0 && l < 16) {
                fence_proxy_async_cta();
                dsmem_bulk(rb ? rh_d1 : rh_d0, src_rh, 128, mrh_r);
            }
            gna0 = __ldcs(g_G + gbn + gx_a);
            gna1 = __ldcs(g_G + gbn + gx_a + 1);
            gnh0 = __ldcs(g_G + gbn + gx_h);
            gnh1 = __ldcs(g_G + gbn + gx_h + 1);

            mbar_wait(mb_rh, ph);                  // full r*h resident locally
            // ---- h' over r*h ----
            float4 r4[4];
#pragma unroll
            for (int q = 0; q < 4; q++) r4[q] = *(const float4*)&rhbf[rb * 512 + q * 128 + l * 4];
            float c[4];
#pragma unroll
            for (int i = 0; i < 4; i++) {
                float s = 0.f;
#pragma unroll
                for (int q = 0; q < 4; q++) {
                    float4 w4 = *(const float4*)&wAll[(64 + lr0 + i) * 512 + q * 128 + l * 4];
                    s = fmaf(w4.x, r4[q].x, s); s = fmaf(w4.y, r4[q].y, s);
                    s = fmaf(w4.z, r4[q].z, s); s = fmaf(w4.w, r4[q].w, s);
                }
#pragma unroll
                for (int d = 16; d; d >>= 1) s += __shfl_xor_sync(~0u, s, d);
                c[i] = s;
            }
            float hc0 = tanhf(c[half * 2]     + gh0);
            float hc1 = tanhf(c[half * 2 + 1] + gh1);
            mbar_wait(mb_z, ph);                   // z ready (local)
            if (rk == 0) {
                float z0 = zbuf[r0], z1 = zbuf[r0 + 1];
                float ho0 = hbuf[p * 512 + j0 + r0], ho1 = hbuf[p * 512 + j0 + r0 + 1];
                stg_h[r0]     = ho0 + z0 * (hc0 - ho0);
                stg_h[r0 + 1] = ho1 + z1 * (hc1 - ho1);
            }
            asm volatile("bar.sync 1, 256;" ::: "memory");
            if (w == 0 && l < 16) {
                fence_proxy_async_cta();
                dsmem_bulk(p ? h_d0 : h_d1, src_h, 128, mh_r);
            }
        } else {
            // ---- z pre-acts (concurrent with r-warps) ----
            float4 h4[4];
#pragma unroll
            for (int q = 0; q < 4; q++) h4[q] = *(const float4*)&hbuf[p * 512 + q * 128 + l * 4];
            float a[4];
#pragma unroll
            for (int i = 0; i < 4; i++) {
                float s = 0.f;
#pragma unroll
                for (int q = 0; q < 4; q++) {
                    float4 w4 = *(const float4*)&wAll[(32 + lr0 + i) * 512 + q * 128 + l * 4];
                    s = fmaf(w4.x, h4[q].x, s); s = fmaf(w4.y, h4[q].y, s);
                    s = fmaf(w4.z, h4[q].z, s); s = fmaf(w4.w, h4[q].w, s);
                }
#pragma unroll
                for (int d = 16; d; d >>= 1) s += __shfl_xor_sync(~0u, s, d);
                a[i] = s;
            }
            if (rk == 0) {
                zbuf[r0]     = sigmoidf_(a[half * 2]     + ga0);
                zbuf[r0 + 1] = sigmoidf_(a[half * 2 + 1] + ga1);
                mbar_arrive(mb_z);                 // release zbuf (16 arrivals)
            }
            gna0 = __ldcs(g_G + gbn + gx_a);
            gna1 = __ldcs(g_G + gbn + gx_a + 1);
        }
        mbar_wait(mb_h, ph);                       // h(t+1) resident locally
        ga0 = gna0; ga1 = gna1; gh0 = gnh0; gh1 = gnh1;
        ph ^= 1; p ^= 1;
    }

    // classifier: final h in hbuf[0]; rank 0 writes out[b][10]
    if (rank == 0 && w < 10) {
        float s = 0.f;
        for (int k = l; k < DH; k += 32)
            s += hbuf[k] * Wc[(size_t)w * DH + k];
#pragma unroll
        for (int d = 16; d; d >>= 1) s += __shfl_xor_sync(~0u, s, d);
        if (l == 0) out[b * 10 + w] = s;
    }
    cl_sync();                                     // no early-exit vs peer DSMEM
}

extern "C" void kernel_launch(void* const* d_in, const int* in_sizes, int n_in,
                              void* d_out, int out_size) {
    const float* x   = (const float*)d_in[0];
    const float* Wlm = (const float*)d_in[1];
    const float* Wz  = (const float*)d_in[2];
    const float* Wr  = (const float*)d_in[3];
    const float* Wh  = (const float*)d_in[4];
    const float* Wc  = (const float*)d_in[5];
    float* out = (float*)d_out;

    const int smem_bytes = (96 * 512 + 1024 + 1024 + 32 + 32 + 32) * 4 + 24;
    cudaFuncSetAttribute(gru_kernel, cudaFuncAttributeNonPortableClusterSizeAllowed, 1);
    cudaFuncSetAttribute(gru_kernel, cudaFuncAttributeMaxDynamicSharedMemorySize, smem_bytes);

    gemm1_kernel<<<dim3(4, 256), 256>>>(x, Wlm);
    gemm2_kernel<<<dim3(12, 256), 256>>>(Wz, Wr, Wh);
    gru_kernel<<<BATCH * CLUSTER, 512, smem_bytes>>>(Wz, Wr, Wh, Wc, out);
}

// round 10
// speedup vs baseline: 1.1998x; 1.1998x over previous
#include <cuda_runtime.h>
#include <cstdint>
#include <cstddef>

#define S_LEN 4096
#define BATCH 8
#define DH    512
#define DIN   2048
#define M_TOT (S_LEN * BATCH)
#define CLUSTER 16
#define RPC   32

__device__ float g_seq[(size_t)M_TOT * DH];
__device__ float g_G[(size_t)M_TOT * 3 * DH];

// ================= GEMM1: seq = x @ Wlm^T (M=32768,N=512,K=2048) ===============
__global__ __launch_bounds__(256) void gemm1_kernel(const float* __restrict__ x,
                                                    const float* __restrict__ Wlm) {
    __shared__ float As[16][132], Bs[16][132];
    const int m0 = blockIdx.y * 128, n0 = blockIdx.x * 128, tid = threadIdx.x;
    const int tx = tid & 15, ty = tid >> 4;
    float acc[8][8] = {};
    for (int k0 = 0; k0 < DIN; k0 += 16) {
#pragma unroll
        for (int i = 0; i < 2; i++) {
            int f = tid * 2 + i, m = f >> 2, kq = f & 3;
            int gm = m0 + m, b = gm & 7, t = gm >> 3;
            float4 v = *reinterpret_cast<const float4*>(x + ((size_t)b * S_LEN + t) * DIN + k0 + kq * 4);
            As[kq*4+0][m] = v.x; As[kq*4+1][m] = v.y; As[kq*4+2][m] = v.z; As[kq*4+3][m] = v.w;
        }
#pragma unroll
        for (int i = 0; i < 2; i++) {
            int f = tid * 2 + i, n = f >> 2, kq = f & 3;
            float4 v = *reinterpret_cast<const float4*>(Wlm + (size_t)(n0 + n) * DIN + k0 + kq * 4);
            Bs[kq*4+0][n] = v.x; Bs[kq*4+1][n] = v.y; Bs[kq*4+2][n] = v.z; Bs[kq*4+3][n] = v.w;
        }
        __syncthreads();
#pragma unroll
        for (int kk = 0; kk < 16; kk++) {
            float4 a0 = *(const float4*)&As[kk][ty*8], a1 = *(const float4*)&As[kk][ty*8+4];
            float4 b0 = *(const float4*)&Bs[kk][tx*4], b1 = *(const float4*)&Bs[kk][64+tx*4];
            float a[8] = {a0.x,a0.y,a0.z,a0.w,a1.x,a1.y,a1.z,a1.w};
            float bb[8] = {b0.x,b0.y,b0.z,b0.w,b1.x,b1.y,b1.z,b1.w};
#pragma unroll
            for (int i = 0; i < 8; i++)
#pragma unroll
                for (int j = 0; j < 8; j++) acc[i][j] = fmaf(a[i], bb[j], acc[i][j]);
        }
        __syncthreads();
    }
#pragma unroll
    for (int i = 0; i < 8; i++) {
        size_t row = (size_t)(m0 + ty * 8 + i) * DH;
        *(float4*)&g_seq[row + n0 + tx*4]      = make_float4(acc[i][0],acc[i][1],acc[i][2],acc[i][3]);
        *(float4*)&g_seq[row + n0 + 64 + tx*4] = make_float4(acc[i][4],acc[i][5],acc[i][6],acc[i][7]);
    }
}

// ============ GEMM2: G = seq @ [Wzx|Wrx|Whx]^T (M=32768,N=1536,K=512) ==========
__global__ __launch_bounds__(256) void gemm2_kernel(const float* __restrict__ Wz,
                                                    const float* __restrict__ Wr,
                                                    const float* __restrict__ Wh) {
    __shared__ float As[16][132], Bs[16][132];
    const int m0 = blockIdx.y * 128, n0 = blockIdx.x * 128, tid = threadIdx.x;
    const int tx = tid & 15, ty = tid >> 4;
    const float* base = (n0 < 512) ? Wz : (n0 < 1024) ? Wr : Wh;
    const int br0 = n0 & 511;
    float acc[8][8] = {};
    for (int k0 = 0; k0 < DH; k0 += 16) {
#pragma unroll
        for (int i = 0; i < 2; i++) {
            int f = tid * 2 + i, m = f >> 2, kq = f & 3;
            float4 v = *reinterpret_cast<const float4*>(g_seq + (size_t)(m0 + m) * DH + k0 + kq * 4);
            As[kq*4+0][m] = v.x; As[kq*4+1][m] = v.y; As[kq*4+2][m] = v.z; As[kq*4+3][m] = v.w;
        }
#pragma unroll
        for (int i = 0; i < 2; i++) {
            int f = tid * 2 + i, n = f >> 2, kq = f & 3;
            float4 v = *reinterpret_cast<const float4*>(base + (size_t)(br0 + n) * 1024 + k0 + kq * 4);
            Bs[kq*4+0][n] = v.x; Bs[kq*4+1][n] = v.y; Bs[kq*4+2][n] = v.z; Bs[kq*4+3][n] = v.w;
        }
        __syncthreads();
#pragma unroll
        for (int kk = 0; kk < 16; kk++) {
            float4 a0 = *(const float4*)&As[kk][ty*8], a1 = *(const float4*)&As[kk][ty*8+4];
            float4 b0 = *(const float4*)&Bs[kk][tx*4], b1 = *(const float4*)&Bs[kk][64+tx*4];
            float a[8] = {a0.x,a0.y,a0.z,a0.w,a1.x,a1.y,a1.z,a1.w};
            float bb[8] = {b0.x,b0.y,b0.z,b0.w,b1.x,b1.y,b1.z,b1.w};
#pragma unroll
            for (int i = 0; i < 8; i++)
#pragma unroll
                for (int j = 0; j < 8; j++) acc[i][j] = fmaf(a[i], bb[j], acc[i][j]);
        }
        __syncthreads();
    }
#pragma unroll
    for (int i = 0; i < 8; i++) {
        size_t row = (size_t)(m0 + ty * 8 + i) * 1536;
        *(float4*)&g_G[row + n0 + tx*4]      = make_float4(acc[i][0],acc[i][1],acc[i][2],acc[i][3]);
        *(float4*)&g_G[row + n0 + 64 + tx*4] = make_float4(acc[i][4],acc[i][5],acc[i][6],acc[i][7]);
    }
}

// ================= helpers =================
__device__ __forceinline__ uint32_t smem_u32(const void* p) {
    return (uint32_t)__cvta_generic_to_shared(p);
}
__device__ __forceinline__ uint32_t dsmem_map(uint32_t a, unsigned r) {
    uint32_t x; asm("mapa.shared::cluster.u32 %0, %1, %2;" : "=r"(x) : "r"(a), "r"(r)); return x;
}
// remote smem 16B store with tx credit on the destination CTA's mbarrier
__device__ __forceinline__ void st_async128(uint32_t a, uint32_t mbar,
                                            float x, float y, float z, float w) {
    asm volatile("st.async.shared::cluster.mbarrier::complete_tx::bytes.v4.b32 "
                 "[%0], {%1,%2,%3,%4}, [%5];"
                 :: "r"(a), "r"(__float_as_uint(x)), "r"(__float_as_uint(y)),
                    "r"(__float_as_uint(z)), "r"(__float_as_uint(w)), "r"(mbar) : "memory");
}
__device__ __forceinline__ void mbar_init(uint32_t a, uint32_t cnt) {
    asm volatile("mbarrier.init.shared.b64 [%0], %1;" :: "r"(a), "r"(cnt) : "memory");
}
__device__ __forceinline__ void mbar_arrive(uint32_t a) {
    asm volatile("mbarrier.arrive.shared.b64 _, [%0];" :: "r"(a) : "memory");
}
__device__ __forceinline__ void mbar_expect_tx(uint32_t a, uint32_t tx) {
    asm volatile("mbarrier.arrive.expect_tx.shared.b64 _, [%0], %1;" :: "r"(a), "r"(tx) : "memory");
}
__device__ __forceinline__ void mbar_wait(uint32_t a, uint32_t parity) {
    uint32_t done;
    asm volatile("{\n\t.reg .pred p;\n\t"
                 "mbarrier.try_wait.parity.shared.b64 p, [%1], %2;\n\t"
                 "selp.b32 %0, 1, 0, p;\n\t}"
                 : "=r"(done) : "r"(a), "r"(parity) : "memory");
    while (!done) {
        asm volatile("{\n\t.reg .pred p;\n\t"
                     "mbarrier.try_wait.parity.shared.b64 p, [%1], %2;\n\t"
                     "selp.b32 %0, 1, 0, p;\n\t}"
                     : "=r"(done) : "r"(a), "r"(parity) : "memory");
    }
}
__device__ __forceinline__ void cl_sync() {
    asm volatile("barrier.cluster.arrive.aligned;" ::: "memory");
    asm volatile("barrier.cluster.wait.aligned;"   ::: "memory");
}
__device__ __forceinline__ float sigmoidf_(float v) { return 1.f / (1.f + __expf(-v)); }
__device__ __forceinline__ float tanh_fast(float v) {
    float y; asm("tanh.approx.f32 %0, %1;" : "=f"(y) : "f"(v)); return y;
}

// == GRU: 8 clusters x 16 CTAs x 512 thr; v4 st.async exchange ==================
__global__ void __cluster_dims__(CLUSTER, 1, 1) __launch_bounds__(512, 1)
gru_kernel(const float* __restrict__ Wz, const float* __restrict__ Wr,
           const float* __restrict__ Wh, const float* __restrict__ Wc,
           float* __restrict__ out) {
    extern __shared__ float sm[];
    float* wAll = sm;                    // [96][512]: r 0-31, z 32-63, h 64-95
    float* hbuf = sm + 96 * 512;         // [2][512]
    float* rhbf = hbuf + 1024;           // [2][512]
    float* zbuf = rhbf + 1024;           // [32]
    uint32_t mb_rh = smem_u32(zbuf + 32);    // 8B each
    uint32_t mb_h  = mb_rh + 8;
    uint32_t mb_z  = mb_rh + 16;

    const int tid = threadIdx.x;
    unsigned rank; asm("mov.u32 %0, %%cluster_ctarank;" : "=r"(rank));
    const int b  = blockIdx.x / CLUSTER;
    const int j0 = (int)rank * RPC;
    const int w = tid >> 5, l = tid & 31;

    for (int i = tid; i < 32 * 128; i += 512) {
        int r = i >> 7, q = (i & 127) * 4;
        *(float4*)&wAll[r * 512 + q]        = *(const float4*)(Wr + (size_t)(j0 + r) * 1024 + 512 + q);
        *(float4*)&wAll[(32 + r) * 512 + q] = *(const float4*)(Wz + (size_t)(j0 + r) * 1024 + 512 + q);
        *(float4*)&wAll[(64 + r) * 512 + q] = *(const float4*)(Wh + (size_t)(j0 + r) * 1024 + 512 + q);
    }
    for (int i = tid; i < 1024; i += 512) hbuf[i] = 0.f;
    if (tid == 0) { mbar_init(mb_rh, 1); mbar_init(mb_h, 1); mbar_init(mb_z, 8); }
    __syncthreads();

    const bool isR = (w < 8);
    const int lw  = isR ? w : (w - 8);
    const int lr0 = lw * 4;                        // this warp's 4 local rows

    // v4 push endpoints: lane l<16 of each r-warp pushes its warp's 4 rows to rank l
    uint32_t rh_d0 = 0, rh_d1 = 0, h_d0 = 0, h_d1 = 0, mrh_r = 0, mh_r = 0;
    if (isR && l < 16) {
        rh_d0 = dsmem_map(smem_u32(&rhbf[0 * 512 + j0 + lr0]), (unsigned)l);
        rh_d1 = dsmem_map(smem_u32(&rhbf[1 * 512 + j0 + lr0]), (unsigned)l);
        h_d0  = dsmem_map(smem_u32(&hbuf[0 * 512 + j0 + lr0]), (unsigned)l);
        h_d1  = dsmem_map(smem_u32(&hbuf[1 * 512 + j0 + lr0]), (unsigned)l);
        mrh_r = dsmem_map(mb_rh, (unsigned)l);
        mh_r  = dsmem_map(mb_h, (unsigned)l);
    }

    // gate-x offsets (one float4 per warp, rows lr0..lr0+3)
    const size_t gx_a = (isR ? 512 : 0) + j0 + lr0;  // r- or z-column block
    const size_t gx_h = 1024 + j0 + lr0;

    cl_sync();                                    // mbars + h0 + weights live

    float4 ga = *(const float4*)(g_G + (size_t)b * 1536 + gx_a);
    float4 gh = make_float4(0.f, 0.f, 0.f, 0.f);
    if (isR) gh = *(const float4*)(g_G + (size_t)b * 1536 + gx_h);

    int p = 0;
    uint32_t ph = 0;
    for (int t = 0; t < S_LEN; t++) {
        if (tid == 0) {                            // arm tx budgets (128 x 16B)
            mbar_expect_tx(mb_rh, 2048);
            mbar_expect_tx(mb_h, 2048);
        }
        const int tn = (t + 1 < S_LEN) ? t + 1 : t;
        const size_t gbn = ((size_t)tn * 8 + b) * 1536;
        float4 gna, gnh = make_float4(0.f, 0.f, 0.f, 0.f);
        const int rb = t & 1;

        if (isR) {
            // ---- r pre-acts (4 rows), push r*h as one v4 per lane<16 ----
            float4 h4[4];
#pragma unroll
            for (int q = 0; q < 4; q++) h4[q] = *(const float4*)&hbuf[p * 512 + q * 128 + l * 4];
            float a[4];
#pragma unroll
            for (int i = 0; i < 4; i++) {
                float s = 0.f;
#pragma unroll
                for (int q = 0; q < 4; q++) {
                    float4 w4 = *(const float4*)&wAll[(lr0 + i) * 512 + q * 128 + l * 4];
                    s = fmaf(w4.x, h4[q].x, s); s = fmaf(w4.y, h4[q].y, s);
                    s = fmaf(w4.z, h4[q].z, s); s = fmaf(w4.w, h4[q].w, s);
                }
#pragma unroll
                for (int d = 16; d; d >>= 1) s += __shfl_xor_sync(~0u, s, d);
                a[i] = s;                          // full sum in ALL lanes
            }
            if (l < 16) {
                float4 ho = *(const float4*)&hbuf[p * 512 + j0 + lr0];
                float rh0 = sigmoidf_(a[0] + ga.x) * ho.x;
                float rh1 = sigmoidf_(a[1] + ga.y) * ho.y;
                float rh2 = sigmoidf_(a[2] + ga.z) * ho.z;
                float rh3 = sigmoidf_(a[3] + ga.w) * ho.w;
                st_async128(rb ? rh_d1 : rh_d0, mrh_r, rh0, rh1, rh2, rh3);
            }
            gna = *(const float4*)(g_G + gbn + gx_a);     // prefetch t+1
            gnh = *(const float4*)(g_G + gbn + gx_h);

            mbar_wait(mb_rh, ph);                  // full r*h resident locally
            // ---- h' (4 rows) over r*h ----
            float4 r4[4];
#pragma unroll
            for (int q = 0; q < 4; q++) r4[q] = *(const float4*)&rhbf[rb * 512 + q * 128 + l * 4];
            float c[4];
#pragma unroll
            for (int i = 0; i < 4; i++) {
                float s = 0.f;
#pragma unroll
                for (int q = 0; q < 4; q++) {
                    float4 w4 = *(const float4*)&wAll[(64 + lr0 + i) * 512 + q * 128 + l * 4];
                    s = fmaf(w4.x, r4[q].x, s); s = fmaf(w4.y, r4[q].y, s);
                    s = fmaf(w4.z, r4[q].z, s); s = fmaf(w4.w, r4[q].w, s);
                }
#pragma unroll
                for (int d = 16; d; d >>= 1) s += __shfl_xor_sync(~0u, s, d);
                c[i] = s;
            }
            mbar_wait(mb_z, ph);                   // z ready (local)
            if (l < 16) {
                float4 zv = *(const float4*)&zbuf[lr0];
                float4 ho = *(const float4*)&hbuf[p * 512 + j0 + lr0];
                float hn0 = ho.x + zv.x * (tanh_fast(c[0] + gh.x) - ho.x);
                float hn1 = ho.y + zv.y * (tanh_fast(c[1] + gh.y) - ho.y);
                float hn2 = ho.z + zv.z * (tanh_fast(c[2] + gh.z) - ho.z);
                float hn3 = ho.w + zv.w * (tanh_fast(c[3] + gh.w) - ho.w);
                st_async128(p ? h_d0 : h_d1, mh_r, hn0, hn1, hn2, hn3);
            }
        } else {
            // ---- z pre-acts (concurrent with r-warps) ----
            float4 h4[4];
#pragma unroll
            for (int q = 0; q < 4; q++) h4[q] = *(const float4*)&hbuf[p * 512 + q * 128 + l * 4];
            float a[4];
#pragma unroll
            for (int i = 0; i < 4; i++) {
                float s = 0.f;
#pragma unroll
                for (int q = 0; q < 4; q++) {
                    float4 w4 = *(const float4*)&wAll[(32 + lr0 + i) * 512 + q * 128 + l * 4];
                    s = fmaf(w4.x, h4[q].x, s); s = fmaf(w4.y, h4[q].y, s);
                    s = fmaf(w4.z, h4[q].z, s); s = fmaf(w4.w, h4[q].w, s);
                }
#pragma unroll
                for (int d = 16; d; d >>= 1) s += __shfl_xor_sync(~0u, s, d);
                a[i] = s;
            }
            if (l == 0) {
                float4 zv = make_float4(sigmoidf_(a[0] + ga.x), sigmoidf_(a[1] + ga.y),
                                        sigmoidf_(a[2] + ga.z), sigmoidf_(a[3] + ga.w));
                *(float4*)&zbuf[lr0] = zv;         // one STS.128
                mbar_arrive(mb_z);                 // release (8 arrivals total)
            }
            gna = *(const float4*)(g_G + gbn + gx_a);
        }
        mbar_wait(mb_h, ph);                       // h(t+1) resident locally
        ga = gna; gh = gnh;
        ph ^= 1; p ^= 1;
    }

    // classifier: final h in hbuf[0]; rank 0 writes out[b][10]
    if (rank == 0 && w < 10) {
        float s = 0.f;
        for (int k = l; k < DH; k += 32)
            s += hbuf[k] * Wc[(size_t)w * DH + k];
#pragma unroll
        for (int d = 16; d; d >>= 1) s += __shfl_xor_sync(~0u, s, d);
        if (l == 0) out[b * 10 + w] = s;
    }
    cl_sync();                                     // no early-exit vs peer DSMEM
}

extern "C" void kernel_launch(void* const* d_in, const int* in_sizes, int n_in,
                              void* d_out, int out_size) {
    const float* x   = (const float*)d_in[0];
    const float* Wlm = (const float*)d_in[1];
    const float* Wz  = (const float*)d_in[2];
    const float* Wr  = (const float*)d_in[3];
    const float* Wh  = (const float*)d_in[4];
    const float* Wc  = (const float*)d_in[5];
    float* out = (float*)d_out;

    const int smem_bytes = (96 * 512 + 1024 + 1024 + 32) * 4 + 24;
    cudaFuncSetAttribute(gru_kernel, cudaFuncAttributeNonPortableClusterSizeAllowed, 1);
    cudaFuncSetAttribute(gru_kernel, cudaFuncAttributeMaxDynamicSharedMemorySize, smem_bytes);

    gemm1_kernel<<<dim3(4, 256), 256>>>(x, Wlm);
    gemm2_kernel<<<dim3(12, 256), 256>>>(Wz, Wr, Wh);
    gru_kernel<<<BATCH * CLUSTER, 512, smem_bytes>>>(Wz, Wr, Wh, Wc, out);
}